// round 4
// baseline (speedup 1.0000x reference)
#include <cuda_runtime.h>
#include <math.h>
#include <stdint.h>

// ---------------------------------------------------------------------------
// RotarySelfAttention: x[B,T,C] -> QKV GEMM(+fused RoPE) -> attention -> proj
// B=2, T=2048, C=1024, H=16, D=64
// Round 4: double-buffered tf32 GEMM, RoPE fused into QKV epilogue,
//          attention widened to 128 queries / 8 warps per block.
// ---------------------------------------------------------------------------

namespace {

constexpr int B_   = 2;
constexpr int T_   = 2048;
constexpr int C_   = 1024;
constexpr int NH   = 16;
constexpr int HD   = 64;
constexpr int MTOK = B_ * T_;   // 4096

// Scratch (allocation-free rule: __device__ globals)
__device__ float g_q[(size_t)B_ * NH * T_ * HD];   // [B,H,T,D] (scaled, tf32)
__device__ float g_k[(size_t)B_ * NH * T_ * HD];
__device__ float g_v[(size_t)B_ * NH * T_ * HD];
__device__ float g_ctx[(size_t)MTOK * C_];         // [B,T,C]
__device__ float g_sc[(size_t)T_ * 32 * 2];        // sin/cos table [t][d][2]

__device__ __forceinline__ float tf32r(float x) {
    uint32_t u;
    asm("cvt.rna.tf32.f32 %0, %1;" : "=r"(u) : "f"(x));
    return __uint_as_float(u);
}

__device__ __forceinline__ void mma_tf32(float c[4], const float a[4], float b0, float b1) {
    asm volatile(
        "mma.sync.aligned.m16n8k8.row.col.f32.tf32.tf32.f32 "
        "{%0,%1,%2,%3}, {%4,%5,%6,%7}, {%8,%9}, {%0,%1,%2,%3};\n"
        : "+f"(c[0]), "+f"(c[1]), "+f"(c[2]), "+f"(c[3])
        : "r"(__float_as_uint(a[0])), "r"(__float_as_uint(a[1])),
          "r"(__float_as_uint(a[2])), "r"(__float_as_uint(a[3])),
          "r"(__float_as_uint(b0)),  "r"(__float_as_uint(b1)));
}

// ---------------------------------------------------------------------------
// sin/cos table: g_sc[(t*32+d)*2] = sin(t * 10000^(-d/32)), +1 = cos
// ---------------------------------------------------------------------------
__global__ __launch_bounds__(256)
void trig_kernel(float* __restrict__ sc)
{
    const int idx = blockIdx.x * 256 + threadIdx.x;   // 65536
    const int d = idx & 31;
    const int t = idx >> 5;
    const float inv_freq = expf((float)d * -0.28782313662425574f); // -ln(1e4)/32
    float s, c;
    sincosf((float)t * inv_freq, &s, &c);
    sc[idx * 2]     = s;
    sc[idx * 2 + 1] = c;
}

// ---------------------------------------------------------------------------
// tf32 tensor-core GEMM, double-buffered smem.
// Block 128x128x16, 128 threads = 4 warps (2x2), warp tile 64x64.
// ROPE=true : QKV GEMM. Epilogue applies bias + rotary and scatters
//             tf32-rounded q/k/v into [B,H,T,D]. Each 64-wide warp tile is
//             exactly one head of one of q/k/v; pair (d,d+32) = acc j, j+4.
// ROPE=false: plain bias epilogue to Cout.
// ---------------------------------------------------------------------------
constexpr int GAS = 20;    // As row stride (floats)
constexpr int GBS = 136;   // Bs row stride (floats)

template<bool ROPE>
__global__ __launch_bounds__(128)
void gemm_tf32(const float* __restrict__ A,
               const float* __restrict__ Bm,
               const float* __restrict__ bias,
               float* __restrict__ Cout,
               float* __restrict__ gq,
               float* __restrict__ gk,
               float* __restrict__ gv,
               const float* __restrict__ sc,
               int M, int N, int K)
{
    __shared__ float As[2][128 * GAS];   // [m][k]
    __shared__ float Bs[2][16 * GBS];    // [k][n]

    const int tid  = threadIdx.x;
    const int lane = tid & 31;
    const int wid  = tid >> 5;
    const int lq   = lane >> 2;
    const int lr   = lane & 3;

    const int brow = blockIdx.y * 128;
    const int bcol = blockIdx.x * 128;
    const int wm   = (wid & 1) * 64;
    const int wn   = (wid >> 1) * 64;

    // global load mappings: A row per thread (16 floats), B 4 float4 per thread
    const int bColl = (lane << 2) + ((wid & 3) << 7); // unused fallback
    (void)bColl;
    const int bkRow = tid >> 5;          // 0..3 (+4q)
    const int bCol4 = (tid & 31) << 2;   // 0..124

    float acc[4][8][4];
#pragma unroll
    for (int i = 0; i < 4; i++)
#pragma unroll
        for (int j = 0; j < 8; j++)
#pragma unroll
            for (int t = 0; t < 4; t++) acc[i][j][t] = 0.f;

    float4 ar[4], br[4];

    // prologue: prefetch tile 0
#pragma unroll
    for (int q = 0; q < 4; q++)
        ar[q] = *(const float4*)&A[(size_t)(brow + tid) * K + q * 4];
#pragma unroll
    for (int q = 0; q < 4; q++)
        br[q] = *(const float4*)&Bm[(size_t)(bkRow + q * 4) * N + bcol + bCol4];

    // store stage 0
#pragma unroll
    for (int q = 0; q < 4; q++) {
        float4 t4 = ar[q];
        t4.x = tf32r(t4.x); t4.y = tf32r(t4.y); t4.z = tf32r(t4.z); t4.w = tf32r(t4.w);
        *(float4*)&As[0][tid * GAS + q * 4] = t4;
    }
#pragma unroll
    for (int q = 0; q < 4; q++) {
        float4 t4 = br[q];
        t4.x = tf32r(t4.x); t4.y = tf32r(t4.y); t4.z = tf32r(t4.z); t4.w = tf32r(t4.w);
        *(float4*)&Bs[0][(bkRow + q * 4) * GBS + bCol4] = t4;
    }
    __syncthreads();

    for (int k0 = 0; k0 < K; k0 += 16) {
        const int st = (k0 >> 4) & 1;
        const bool more = (k0 + 16) < K;

        if (more) {
#pragma unroll
            for (int q = 0; q < 4; q++)
                ar[q] = *(const float4*)&A[(size_t)(brow + tid) * K + k0 + 16 + q * 4];
#pragma unroll
            for (int q = 0; q < 4; q++)
                br[q] = *(const float4*)&Bm[(size_t)(k0 + 16 + bkRow + q * 4) * N + bcol + bCol4];
        }

        // compute on stage st
#pragma unroll
        for (int kk = 0; kk < 16; kk += 8) {
            float a[4][4];
#pragma unroll
            for (int i = 0; i < 4; i++) {
                const int m = wm + i * 16 + lq;
                a[i][0] = As[st][m * GAS + kk + lr];
                a[i][1] = As[st][(m + 8) * GAS + kk + lr];
                a[i][2] = As[st][m * GAS + kk + lr + 4];
                a[i][3] = As[st][(m + 8) * GAS + kk + lr + 4];
            }
#pragma unroll
            for (int j = 0; j < 8; j++) {
                const int n = wn + j * 8 + lq;
                const float b0 = Bs[st][(kk + lr) * GBS + n];
                const float b1 = Bs[st][(kk + lr + 4) * GBS + n];
#pragma unroll
                for (int i = 0; i < 4; i++)
                    mma_tf32(acc[i][j], a[i], b0, b1);
            }
        }

        // store next tile into the other stage
        if (more) {
            const int ns = st ^ 1;
#pragma unroll
            for (int q = 0; q < 4; q++) {
                float4 t4 = ar[q];
                t4.x = tf32r(t4.x); t4.y = tf32r(t4.y); t4.z = tf32r(t4.z); t4.w = tf32r(t4.w);
                *(float4*)&As[ns][tid * GAS + q * 4] = t4;
            }
#pragma unroll
            for (int q = 0; q < 4; q++) {
                float4 t4 = br[q];
                t4.x = tf32r(t4.x); t4.y = tf32r(t4.y); t4.z = tf32r(t4.z); t4.w = tf32r(t4.w);
                *(float4*)&Bs[ns][(bkRow + q * 4) * GBS + bCol4] = t4;
            }
        }
        __syncthreads();
    }

    if (!ROPE) {
        // ---- plain bias epilogue ----
#pragma unroll
        for (int i = 0; i < 4; i++) {
            const int row0 = brow + wm + i * 16 + lq;
#pragma unroll
            for (int j = 0; j < 8; j++) {
                const int col = bcol + wn + j * 8 + lr * 2;
                const float bi0 = bias[col], bi1 = bias[col + 1];
                float2 w0, w1;
                w0.x = acc[i][j][0] + bi0; w0.y = acc[i][j][1] + bi1;
                w1.x = acc[i][j][2] + bi0; w1.y = acc[i][j][3] + bi1;
                *(float2*)&Cout[(size_t)row0 * N + col]       = w0;
                *(float2*)&Cout[(size_t)(row0 + 8) * N + col] = w1;
            }
        }
    } else {
        // ---- fused RoPE epilogue: bias + rotate + scatter to [B,H,T,D] ----
        const int colbase = bcol + wn;            // 64-aligned: one head of q/k/v
        const int region  = colbase >> 10;        // 0=q, 1=k, 2=v
        const int h       = (colbase >> 6) & 15;
        float* dst = (region == 0) ? gq : (region == 1) ? gk : gv;
        const float scl = (region == 0) ? 0.125f : 1.0f;

#pragma unroll
        for (int i = 0; i < 4; i++) {
            const int rowA = brow + wm + i * 16 + lq;
#pragma unroll
            for (int half = 0; half < 2; half++) {
                const int row = rowA + half * 8;
                const int t   = row & (T_ - 1);
                const int bb  = row >> 11;
                float* drow = dst + ((size_t)((bb * NH + h) * T_) + t) * HD;
#pragma unroll
                for (int j = 0; j < 4; j++) {
                    const int d0 = j * 8 + lr * 2;             // 0..30
                    const float x10 = acc[i][j][2 * half + 0]     + bias[colbase + d0];
                    const float x11 = acc[i][j][2 * half + 1]     + bias[colbase + d0 + 1];
                    const float x20 = acc[i][j + 4][2 * half + 0] + bias[colbase + d0 + 32];
                    const float x21 = acc[i][j + 4][2 * half + 1] + bias[colbase + d0 + 33];
                    float2 o1, o2;
                    if (region < 2) {
                        const float2 sc0 = *(const float2*)&sc[(t * 32 + d0) * 2];
                        const float2 sc1 = *(const float2*)&sc[(t * 32 + d0 + 1) * 2];
                        o1.x = (x10 * sc0.y - x20 * sc0.x) * scl;
                        o1.y = (x11 * sc1.y - x21 * sc1.x) * scl;
                        o2.x = (x20 * sc0.y + x10 * sc0.x) * scl;
                        o2.y = (x21 * sc1.y + x11 * sc1.x) * scl;
                    } else {
                        o1.x = x10; o1.y = x11; o2.x = x20; o2.y = x21;
                    }
                    o1.x = tf32r(o1.x); o1.y = tf32r(o1.y);
                    o2.x = tf32r(o2.x); o2.y = tf32r(o2.y);
                    *(float2*)&drow[d0]      = o1;
                    *(float2*)&drow[d0 + 32] = o2;
                }
            }
        }
    }
}

// ---------------------------------------------------------------------------
// Flash attention, tf32 mma.sync, fp32 accumulate.
// Block: 256 threads (8 warps), 128 query rows; KV tiles of 64 keys.
// Warp w owns query rows [16w, 16w+16).
// smem (dynamic, 69 KB): Ks[64][68], Vs[64][72], Ps[128][68]
// ---------------------------------------------------------------------------
constexpr int QB  = 128;
constexpr int KBt = 64;
constexpr int KS  = 68;
constexpr int VS  = 72;
constexpr int SMEM_FLOATS = KBt * KS + KBt * VS + QB * KS; // 17664
constexpr int SMEM_BYTES  = SMEM_FLOATS * 4;               // 70656

__global__ __launch_bounds__(256)
void flash_attn_tf32_kernel(const float* __restrict__ q,
                            const float* __restrict__ k,
                            const float* __restrict__ v,
                            float* __restrict__ ctx)
{
    extern __shared__ float sm[];
    float* Ks = sm;                       // [64][68]
    float* Vs = sm + KBt * KS;            // [64][72]
    float* Ps = sm + KBt * KS + KBt * VS; // [128][68]  (Q stage, then P)

    const int tid  = threadIdx.x;
    const int lane = tid & 31;
    const int wid  = tid >> 5;
    const int bh   = blockIdx.y;          // b*NH + h
    const int b    = bh >> 4;
    const int h    = bh & 15;
    const int q0   = blockIdx.x * QB;

    const int lq = lane >> 2;
    const int lr = lane & 3;
    const int r0 = wid * 16 + lq;         // 0..127

    const float NEG_INF = __int_as_float(0xff800000u);

    // ---- stage Q tile, pull A-fragments into registers ----
    const float* qbase = q + ((size_t)bh * T_ + q0) * HD;
#pragma unroll
    for (int i = tid; i < QB * 16; i += 256) {
        const int row = i >> 4, c4 = i & 15;
        *(float4*)&Ps[row * KS + c4 * 4] = *(const float4*)&qbase[(size_t)row * HD + c4 * 4];
    }
    __syncthreads();

    float qf[8][4];
#pragma unroll
    for (int kk = 0; kk < 8; kk++) {
        const int c = kk * 8 + lr;
        qf[kk][0] = Ps[r0 * KS + c];
        qf[kk][1] = Ps[(r0 + 8) * KS + c];
        qf[kk][2] = Ps[r0 * KS + c + 4];
        qf[kk][3] = Ps[(r0 + 8) * KS + c + 4];
    }

    float oacc[8][4];
#pragma unroll
    for (int n = 0; n < 8; n++)
#pragma unroll
        for (int j = 0; j < 4; j++) oacc[n][j] = 0.f;
    float m0 = NEG_INF, m1 = NEG_INF, l0 = 0.f, l1 = 0.f;

    const float* kb = k + (size_t)bh * T_ * HD;
    const float* vb = v + (size_t)bh * T_ * HD;

    for (int kt = 0; kt < T_; kt += KBt) {
        __syncthreads();
#pragma unroll
        for (int i = tid; i < KBt * 16; i += 256) {
            const int row = i >> 4, c4 = i & 15;
            *(float4*)&Ks[row * KS + c4 * 4] = *(const float4*)&kb[(size_t)(kt + row) * HD + c4 * 4];
            *(float4*)&Vs[row * VS + c4 * 4] = *(const float4*)&vb[(size_t)(kt + row) * HD + c4 * 4];
        }
        __syncthreads();

        // ---- S = Q K^T ----
        float sacc[8][4];
#pragma unroll
        for (int n = 0; n < 8; n++)
#pragma unroll
            for (int j = 0; j < 4; j++) sacc[n][j] = 0.f;

#pragma unroll
        for (int kk = 0; kk < 8; kk++) {
#pragma unroll
            for (int n = 0; n < 8; n++) {
                const float b0 = Ks[(n * 8 + lq) * KS + kk * 8 + lr];
                const float b1 = Ks[(n * 8 + lq) * KS + kk * 8 + lr + 4];
                mma_tf32(sacc[n], qf[kk], b0, b1);
            }
        }

        // ---- online softmax ----
        float tm0 = NEG_INF, tm1 = NEG_INF;
#pragma unroll
        for (int n = 0; n < 8; n++) {
            tm0 = fmaxf(tm0, fmaxf(sacc[n][0], sacc[n][1]));
            tm1 = fmaxf(tm1, fmaxf(sacc[n][2], sacc[n][3]));
        }
        tm0 = fmaxf(tm0, __shfl_xor_sync(0xffffffffu, tm0, 1));
        tm0 = fmaxf(tm0, __shfl_xor_sync(0xffffffffu, tm0, 2));
        tm1 = fmaxf(tm1, __shfl_xor_sync(0xffffffffu, tm1, 1));
        tm1 = fmaxf(tm1, __shfl_xor_sync(0xffffffffu, tm1, 2));

        const float mn0 = fmaxf(m0, tm0), mn1 = fmaxf(m1, tm1);
        const float a0 = __expf(m0 - mn0), a1 = __expf(m1 - mn1);
        l0 *= a0; l1 *= a1;
#pragma unroll
        for (int n = 0; n < 8; n++) {
            oacc[n][0] *= a0; oacc[n][1] *= a0;
            oacc[n][2] *= a1; oacc[n][3] *= a1;
        }
        m0 = mn0; m1 = mn1;

        // ---- P = exp(S - m), tf32, warp-private Ps rows ----
#pragma unroll
        for (int n = 0; n < 8; n++) {
            const float p0 = __expf(sacc[n][0] - mn0);
            const float p1 = __expf(sacc[n][1] - mn0);
            const float p2 = __expf(sacc[n][2] - mn1);
            const float p3 = __expf(sacc[n][3] - mn1);
            l0 += p0 + p1; l1 += p2 + p3;
            float2 s01, s23;
            s01.x = tf32r(p0); s01.y = tf32r(p1);
            s23.x = tf32r(p2); s23.y = tf32r(p3);
            *(float2*)&Ps[r0 * KS + n * 8 + lr * 2]       = s01;
            *(float2*)&Ps[(r0 + 8) * KS + n * 8 + lr * 2] = s23;
        }
        __syncwarp();

        // ---- O += P V ----
#pragma unroll
        for (int kk = 0; kk < 8; kk++) {
            float af[4];
            af[0] = Ps[r0 * KS + kk * 8 + lr];
            af[1] = Ps[(r0 + 8) * KS + kk * 8 + lr];
            af[2] = Ps[r0 * KS + kk * 8 + lr + 4];
            af[3] = Ps[(r0 + 8) * KS + kk * 8 + lr + 4];
#pragma unroll
            for (int n = 0; n < 8; n++) {
                const float b0 = Vs[(kk * 8 + lr) * VS + n * 8 + lq];
                const float b1 = Vs[(kk * 8 + lr + 4) * VS + n * 8 + lq];
                mma_tf32(oacc[n], af, b0, b1);
            }
        }
    }

    // ---- epilogue ----
    l0 += __shfl_xor_sync(0xffffffffu, l0, 1);
    l0 += __shfl_xor_sync(0xffffffffu, l0, 2);
    l1 += __shfl_xor_sync(0xffffffffu, l1, 1);
    l1 += __shfl_xor_sync(0xffffffffu, l1, 2);
    const float inv0 = 1.f / l0, inv1 = 1.f / l1;

    float* ob0 = ctx + ((size_t)(b * T_) + q0 + r0) * C_ + h * HD;
    float* ob1 = ob0 + (size_t)8 * C_;
#pragma unroll
    for (int n = 0; n < 8; n++) {
        float2 w0, w1;
        w0.x = oacc[n][0] * inv0; w0.y = oacc[n][1] * inv0;
        w1.x = oacc[n][2] * inv1; w1.y = oacc[n][3] * inv1;
        *(float2*)&ob0[n * 8 + lr * 2] = w0;
        *(float2*)&ob1[n * 8 + lr * 2] = w1;
    }
}

} // anonymous namespace

// ---------------------------------------------------------------------------
extern "C" void kernel_launch(void* const* d_in, const int* in_sizes, int n_in,
                              void* d_out, int out_size)
{
    const float* x     = (const float*)d_in[0];
    const float* W_qkv = (const float*)d_in[1];
    const float* b_qkv = (const float*)d_in[2];
    const float* W_out = (const float*)d_in[3];
    const float* b_out = (const float*)d_in[4];
    float* out = (float*)d_out;

    float *qp, *kp, *vp, *ctx, *scp;
    cudaGetSymbolAddress((void**)&qp,  g_q);
    cudaGetSymbolAddress((void**)&kp,  g_k);
    cudaGetSymbolAddress((void**)&vp,  g_v);
    cudaGetSymbolAddress((void**)&ctx, g_ctx);
    cudaGetSymbolAddress((void**)&scp, g_sc);

    // 0) sin/cos table
    trig_kernel<<<(T_ * 32) / 256, 256>>>(scp);

    // 1) QKV GEMM with fused bias + RoPE + scatter to [B,H,T,D]
    {
        dim3 grid(3 * C_ / 128, MTOK / 128);
        gemm_tf32<true><<<grid, 128>>>(x, W_qkv, b_qkv, nullptr,
                                       qp, kp, vp, scp, MTOK, 3 * C_, C_);
    }

    // 2) Flash attention (tf32 tensor cores)
    {
        cudaFuncSetAttribute(flash_attn_tf32_kernel,
                             cudaFuncAttributeMaxDynamicSharedMemorySize, SMEM_BYTES);
        dim3 grid(T_ / QB, B_ * NH);
        flash_attn_tf32_kernel<<<grid, 256, SMEM_BYTES>>>(qp, kp, vp, ctx);
    }

    // 3) Output projection
    {
        dim3 grid(C_ / 128, MTOK / 128);
        gemm_tf32<false><<<grid, 128>>>(ctx, W_out, b_out, out,
                                        nullptr, nullptr, nullptr, nullptr,
                                        MTOK, C_, C_);
    }
}

// round 5
// speedup vs baseline: 1.2378x; 1.2378x over previous
#include <cuda_runtime.h>
#include <math.h>
#include <stdint.h>

// ---------------------------------------------------------------------------
// RotarySelfAttention: x[B,T,C] -> QKV GEMM(+fused RoPE) -> attention -> proj
// B=2, T=2048, C=1024, H=16, D=64
// Round 5: double-buffered tf32 GEMM with the round-3 COALESCED load mapping
//          (round-4 regression was the uncoalesced A loads), fused RoPE kept,
//          attention reverted to proven round-3 shape (QB=64, 4 warps).
// ---------------------------------------------------------------------------

namespace {

constexpr int B_   = 2;
constexpr int T_   = 2048;
constexpr int C_   = 1024;
constexpr int NH   = 16;
constexpr int HD   = 64;
constexpr int MTOK = B_ * T_;   // 4096

// Scratch (allocation-free rule: __device__ globals)
__device__ float g_q[(size_t)B_ * NH * T_ * HD];   // [B,H,T,D] (scaled, tf32)
__device__ float g_k[(size_t)B_ * NH * T_ * HD];
__device__ float g_v[(size_t)B_ * NH * T_ * HD];
__device__ float g_ctx[(size_t)MTOK * C_];         // [B,T,C]
__device__ float g_sc[(size_t)T_ * 32 * 2];        // sin/cos table [t][d][2]

__device__ __forceinline__ float tf32r(float x) {
    uint32_t u;
    asm("cvt.rna.tf32.f32 %0, %1;" : "=r"(u) : "f"(x));
    return __uint_as_float(u);
}

__device__ __forceinline__ void mma_tf32(float c[4], const float a[4], float b0, float b1) {
    asm volatile(
        "mma.sync.aligned.m16n8k8.row.col.f32.tf32.tf32.f32 "
        "{%0,%1,%2,%3}, {%4,%5,%6,%7}, {%8,%9}, {%0,%1,%2,%3};\n"
        : "+f"(c[0]), "+f"(c[1]), "+f"(c[2]), "+f"(c[3])
        : "r"(__float_as_uint(a[0])), "r"(__float_as_uint(a[1])),
          "r"(__float_as_uint(a[2])), "r"(__float_as_uint(a[3])),
          "r"(__float_as_uint(b0)),  "r"(__float_as_uint(b1)));
}

// ---------------------------------------------------------------------------
// sin/cos table: g_sc[(t*32+d)*2] = sin(t * 10000^(-d/32)), +1 = cos
// ---------------------------------------------------------------------------
__global__ __launch_bounds__(256)
void trig_kernel(float* __restrict__ sc)
{
    const int idx = blockIdx.x * 256 + threadIdx.x;   // 65536
    const int d = idx & 31;
    const int t = idx >> 5;
    const float inv_freq = expf((float)d * -0.28782313662425574f); // -ln(1e4)/32
    float s, c;
    sincosf((float)t * inv_freq, &s, &c);
    sc[idx * 2]     = s;
    sc[idx * 2 + 1] = c;
}

// ---------------------------------------------------------------------------
// tf32 tensor-core GEMM, double-buffered smem, coalesced loads.
// Block 128x128x16, 128 threads = 4 warps (2x2), warp tile 64x64.
// A loads: thread tid -> rows (tid>>2)+p*32, cols (tid&3)*4 (64B warp rows).
// B loads: thread tid -> row tid>>3, cols (tid&7)*4 + j*32 (coalesced 512B).
// ROPE=true : epilogue applies bias + rotary, scatters tf32 q/k/v [B,H,T,D].
// ROPE=false: plain bias epilogue to Cout.
// ---------------------------------------------------------------------------
constexpr int GAS = 20;    // As row stride (floats)
constexpr int GBS = 136;   // Bs row stride (floats)

template<bool ROPE>
__global__ __launch_bounds__(128)
void gemm_tf32(const float* __restrict__ A,
               const float* __restrict__ Bm,
               const float* __restrict__ bias,
               float* __restrict__ Cout,
               float* __restrict__ gq,
               float* __restrict__ gk,
               float* __restrict__ gv,
               const float* __restrict__ sc,
               int M, int N, int K)
{
    __shared__ float As[2][128 * GAS];   // [m][k]
    __shared__ float Bs[2][16 * GBS];    // [k][n]

    const int tid  = threadIdx.x;
    const int lane = tid & 31;
    const int wid  = tid >> 5;
    const int lq   = lane >> 2;
    const int lr   = lane & 3;

    const int brow = blockIdx.y * 128;
    const int bcol = blockIdx.x * 128;
    const int wm   = (wid & 1) * 64;
    const int wn   = (wid >> 1) * 64;

    // coalesced global->reg load mappings (round-3 proven)
    const int aRow = tid >> 2;          // 0..31 (+p*32)
    const int aCol = (tid & 3) * 4;     // 0,4,8,12
    const int bRow = tid >> 3;          // 0..15
    const int bCol = (tid & 7) * 4;     // 0..28 (+j*32)

    float acc[4][8][4];
#pragma unroll
    for (int i = 0; i < 4; i++)
#pragma unroll
        for (int j = 0; j < 8; j++)
#pragma unroll
            for (int t = 0; t < 4; t++) acc[i][j][t] = 0.f;

    float4 ar[4], br[4];

    // prologue: prefetch tile 0, store to stage 0
#pragma unroll
    for (int p = 0; p < 4; p++)
        ar[p] = *(const float4*)&A[(size_t)(brow + aRow + p * 32) * K + aCol];
#pragma unroll
    for (int j = 0; j < 4; j++)
        br[j] = *(const float4*)&Bm[(size_t)bRow * N + bcol + bCol + j * 32];

#pragma unroll
    for (int p = 0; p < 4; p++) {
        float4 t4 = ar[p];
        t4.x = tf32r(t4.x); t4.y = tf32r(t4.y); t4.z = tf32r(t4.z); t4.w = tf32r(t4.w);
        *(float4*)&As[0][(aRow + p * 32) * GAS + aCol] = t4;
    }
#pragma unroll
    for (int j = 0; j < 4; j++) {
        float4 t4 = br[j];
        t4.x = tf32r(t4.x); t4.y = tf32r(t4.y); t4.z = tf32r(t4.z); t4.w = tf32r(t4.w);
        *(float4*)&Bs[0][bRow * GBS + bCol + j * 32] = t4;
    }
    __syncthreads();

    for (int k0 = 0; k0 < K; k0 += 16) {
        const int st = (k0 >> 4) & 1;
        const bool more = (k0 + 16) < K;

        // prefetch next tile into regs (overlaps with compute below)
        if (more) {
#pragma unroll
            for (int p = 0; p < 4; p++)
                ar[p] = *(const float4*)&A[(size_t)(brow + aRow + p * 32) * K + k0 + 16 + aCol];
#pragma unroll
            for (int j = 0; j < 4; j++)
                br[j] = *(const float4*)&Bm[(size_t)(k0 + 16 + bRow) * N + bcol + bCol + j * 32];
        }

        // compute on stage st
#pragma unroll
        for (int kk = 0; kk < 16; kk += 8) {
            float a[4][4];
#pragma unroll
            for (int i = 0; i < 4; i++) {
                const int m = wm + i * 16 + lq;
                a[i][0] = As[st][m * GAS + kk + lr];
                a[i][1] = As[st][(m + 8) * GAS + kk + lr];
                a[i][2] = As[st][m * GAS + kk + lr + 4];
                a[i][3] = As[st][(m + 8) * GAS + kk + lr + 4];
            }
#pragma unroll
            for (int j = 0; j < 8; j++) {
                const int n = wn + j * 8 + lq;
                const float b0 = Bs[st][(kk + lr) * GBS + n];
                const float b1 = Bs[st][(kk + lr + 4) * GBS + n];
#pragma unroll
                for (int i = 0; i < 4; i++)
                    mma_tf32(acc[i][j], a[i], b0, b1);
            }
        }

        // store next tile into the other stage
        if (more) {
            const int ns = st ^ 1;
#pragma unroll
            for (int p = 0; p < 4; p++) {
                float4 t4 = ar[p];
                t4.x = tf32r(t4.x); t4.y = tf32r(t4.y); t4.z = tf32r(t4.z); t4.w = tf32r(t4.w);
                *(float4*)&As[ns][(aRow + p * 32) * GAS + aCol] = t4;
            }
#pragma unroll
            for (int j = 0; j < 4; j++) {
                float4 t4 = br[j];
                t4.x = tf32r(t4.x); t4.y = tf32r(t4.y); t4.z = tf32r(t4.z); t4.w = tf32r(t4.w);
                *(float4*)&Bs[ns][bRow * GBS + bCol + j * 32] = t4;
            }
        }
        __syncthreads();
    }

    if (!ROPE) {
        // ---- plain bias epilogue ----
#pragma unroll
        for (int i = 0; i < 4; i++) {
            const int row0 = brow + wm + i * 16 + lq;
#pragma unroll
            for (int j = 0; j < 8; j++) {
                const int col = bcol + wn + j * 8 + lr * 2;
                const float bi0 = bias[col], bi1 = bias[col + 1];
                float2 w0, w1;
                w0.x = acc[i][j][0] + bi0; w0.y = acc[i][j][1] + bi1;
                w1.x = acc[i][j][2] + bi0; w1.y = acc[i][j][3] + bi1;
                *(float2*)&Cout[(size_t)row0 * N + col]       = w0;
                *(float2*)&Cout[(size_t)(row0 + 8) * N + col] = w1;
            }
        }
    } else {
        // ---- fused RoPE epilogue: bias + rotate + scatter to [B,H,T,D] ----
        const int colbase = bcol + wn;            // 64-aligned: one head of q/k/v
        const int region  = colbase >> 10;        // 0=q, 1=k, 2=v
        const int h       = (colbase >> 6) & 15;
        float* dst = (region == 0) ? gq : (region == 1) ? gk : gv;
        const float scl = (region == 0) ? 0.125f : 1.0f;

#pragma unroll
        for (int i = 0; i < 4; i++) {
            const int rowA = brow + wm + i * 16 + lq;
#pragma unroll
            for (int half = 0; half < 2; half++) {
                const int row = rowA + half * 8;
                const int t   = row & (T_ - 1);
                const int bb  = row >> 11;
                float* drow = dst + ((size_t)((bb * NH + h) * T_) + t) * HD;
#pragma unroll
                for (int j = 0; j < 4; j++) {
                    const int d0 = j * 8 + lr * 2;             // 0..30
                    const float x10 = acc[i][j][2 * half + 0]     + bias[colbase + d0];
                    const float x11 = acc[i][j][2 * half + 1]     + bias[colbase + d0 + 1];
                    const float x20 = acc[i][j + 4][2 * half + 0] + bias[colbase + d0 + 32];
                    const float x21 = acc[i][j + 4][2 * half + 1] + bias[colbase + d0 + 33];
                    float2 o1, o2;
                    if (region < 2) {
                        const float2 sc0 = *(const float2*)&sc[(t * 32 + d0) * 2];
                        const float2 sc1 = *(const float2*)&sc[(t * 32 + d0 + 1) * 2];
                        o1.x = (x10 * sc0.y - x20 * sc0.x) * scl;
                        o1.y = (x11 * sc1.y - x21 * sc1.x) * scl;
                        o2.x = (x20 * sc0.y + x10 * sc0.x) * scl;
                        o2.y = (x21 * sc1.y + x11 * sc1.x) * scl;
                    } else {
                        o1.x = x10; o1.y = x11; o2.x = x20; o2.y = x21;
                    }
                    o1.x = tf32r(o1.x); o1.y = tf32r(o1.y);
                    o2.x = tf32r(o2.x); o2.y = tf32r(o2.y);
                    *(float2*)&drow[d0]      = o1;
                    *(float2*)&drow[d0 + 32] = o2;
                }
            }
        }
    }
}

// ---------------------------------------------------------------------------
// Flash attention, tf32 mma.sync, fp32 accumulate. (round-3 proven config)
// Block: 128 threads (4 warps), 64 query rows; KV tiles of 64 keys.
// smem (dynamic, 52 KB): Ks[64][68], Vs[64][72], Ps[64][68]
// ---------------------------------------------------------------------------
constexpr int QB  = 64;
constexpr int KBt = 64;
constexpr int KS  = 68;
constexpr int VS  = 72;
constexpr int SMEM_FLOATS = KBt * KS + KBt * VS + QB * KS; // 13312
constexpr int SMEM_BYTES  = SMEM_FLOATS * 4;               // 53248

__global__ __launch_bounds__(128)
void flash_attn_tf32_kernel(const float* __restrict__ q,
                            const float* __restrict__ k,
                            const float* __restrict__ v,
                            float* __restrict__ ctx)
{
    extern __shared__ float sm[];
    float* Ks = sm;                       // [64][68]
    float* Vs = sm + KBt * KS;            // [64][72]
    float* Ps = sm + KBt * KS + KBt * VS; // [64][68]  (Q stage, then P)

    const int tid  = threadIdx.x;
    const int lane = tid & 31;
    const int wid  = tid >> 5;
    const int bh   = blockIdx.y;          // b*NH + h
    const int b    = bh >> 4;
    const int h    = bh & 15;
    const int q0   = blockIdx.x * QB;

    const int lq = lane >> 2;
    const int lr = lane & 3;
    const int r0 = wid * 16 + lq;

    const float NEG_INF = __int_as_float(0xff800000u);

    // ---- stage Q tile into Ps, pull A-fragments into registers ----
    const float* qbase = q + ((size_t)bh * T_ + q0) * HD;
#pragma unroll
    for (int i = tid; i < QB * 16; i += 128) {
        const int row = i >> 4, c4 = i & 15;
        *(float4*)&Ps[row * KS + c4 * 4] = *(const float4*)&qbase[(size_t)row * HD + c4 * 4];
    }
    __syncthreads();

    float qf[8][4];
#pragma unroll
    for (int kk = 0; kk < 8; kk++) {
        const int c = kk * 8 + lr;
        qf[kk][0] = Ps[r0 * KS + c];
        qf[kk][1] = Ps[(r0 + 8) * KS + c];
        qf[kk][2] = Ps[r0 * KS + c + 4];
        qf[kk][3] = Ps[(r0 + 8) * KS + c + 4];
    }

    float oacc[8][4];
#pragma unroll
    for (int n = 0; n < 8; n++)
#pragma unroll
        for (int j = 0; j < 4; j++) oacc[n][j] = 0.f;
    float m0 = NEG_INF, m1 = NEG_INF, l0 = 0.f, l1 = 0.f;

    const float* kb = k + (size_t)bh * T_ * HD;
    const float* vb = v + (size_t)bh * T_ * HD;

    for (int kt = 0; kt < T_; kt += KBt) {
        __syncthreads();
#pragma unroll
        for (int i = tid; i < KBt * 16; i += 128) {
            const int row = i >> 4, c4 = i & 15;
            *(float4*)&Ks[row * KS + c4 * 4] = *(const float4*)&kb[(size_t)(kt + row) * HD + c4 * 4];
            *(float4*)&Vs[row * VS + c4 * 4] = *(const float4*)&vb[(size_t)(kt + row) * HD + c4 * 4];
        }
        __syncthreads();

        // ---- S = Q K^T ----
        float sacc[8][4];
#pragma unroll
        for (int n = 0; n < 8; n++)
#pragma unroll
            for (int j = 0; j < 4; j++) sacc[n][j] = 0.f;

#pragma unroll
        for (int kk = 0; kk < 8; kk++) {
#pragma unroll
            for (int n = 0; n < 8; n++) {
                const float b0 = Ks[(n * 8 + lq) * KS + kk * 8 + lr];
                const float b1 = Ks[(n * 8 + lq) * KS + kk * 8 + lr + 4];
                mma_tf32(sacc[n], qf[kk], b0, b1);
            }
        }

        // ---- online softmax ----
        float tm0 = NEG_INF, tm1 = NEG_INF;
#pragma unroll
        for (int n = 0; n < 8; n++) {
            tm0 = fmaxf(tm0, fmaxf(sacc[n][0], sacc[n][1]));
            tm1 = fmaxf(tm1, fmaxf(sacc[n][2], sacc[n][3]));
        }
        tm0 = fmaxf(tm0, __shfl_xor_sync(0xffffffffu, tm0, 1));
        tm0 = fmaxf(tm0, __shfl_xor_sync(0xffffffffu, tm0, 2));
        tm1 = fmaxf(tm1, __shfl_xor_sync(0xffffffffu, tm1, 1));
        tm1 = fmaxf(tm1, __shfl_xor_sync(0xffffffffu, tm1, 2));

        const float mn0 = fmaxf(m0, tm0), mn1 = fmaxf(m1, tm1);
        const float a0 = __expf(m0 - mn0), a1 = __expf(m1 - mn1);
        l0 *= a0; l1 *= a1;
#pragma unroll
        for (int n = 0; n < 8; n++) {
            oacc[n][0] *= a0; oacc[n][1] *= a0;
            oacc[n][2] *= a1; oacc[n][3] *= a1;
        }
        m0 = mn0; m1 = mn1;

        // ---- P = exp(S - m), tf32-rounded, warp-private Ps rows ----
#pragma unroll
        for (int n = 0; n < 8; n++) {
            const float p0 = __expf(sacc[n][0] - mn0);
            const float p1 = __expf(sacc[n][1] - mn0);
            const float p2 = __expf(sacc[n][2] - mn1);
            const float p3 = __expf(sacc[n][3] - mn1);
            l0 += p0 + p1; l1 += p2 + p3;
            float2 s01, s23;
            s01.x = tf32r(p0); s01.y = tf32r(p1);
            s23.x = tf32r(p2); s23.y = tf32r(p3);
            *(float2*)&Ps[r0 * KS + n * 8 + lr * 2]       = s01;
            *(float2*)&Ps[(r0 + 8) * KS + n * 8 + lr * 2] = s23;
        }
        __syncwarp();

        // ---- O += P V ----
#pragma unroll
        for (int kk = 0; kk < 8; kk++) {
            float af[4];
            af[0] = Ps[r0 * KS + kk * 8 + lr];
            af[1] = Ps[(r0 + 8) * KS + kk * 8 + lr];
            af[2] = Ps[r0 * KS + kk * 8 + lr + 4];
            af[3] = Ps[(r0 + 8) * KS + kk * 8 + lr + 4];
#pragma unroll
            for (int n = 0; n < 8; n++) {
                const float b0 = Vs[(kk * 8 + lr) * VS + n * 8 + lq];
                const float b1 = Vs[(kk * 8 + lr + 4) * VS + n * 8 + lq];
                mma_tf32(oacc[n], af, b0, b1);
            }
        }
    }

    // ---- epilogue ----
    l0 += __shfl_xor_sync(0xffffffffu, l0, 1);
    l0 += __shfl_xor_sync(0xffffffffu, l0, 2);
    l1 += __shfl_xor_sync(0xffffffffu, l1, 1);
    l1 += __shfl_xor_sync(0xffffffffu, l1, 2);
    const float inv0 = 1.f / l0, inv1 = 1.f / l1;

    float* ob0 = ctx + ((size_t)(b * T_) + q0 + r0) * C_ + h * HD;
    float* ob1 = ob0 + (size_t)8 * C_;
#pragma unroll
    for (int n = 0; n < 8; n++) {
        float2 w0, w1;
        w0.x = oacc[n][0] * inv0; w0.y = oacc[n][1] * inv0;
        w1.x = oacc[n][2] * inv1; w1.y = oacc[n][3] * inv1;
        *(float2*)&ob0[n * 8 + lr * 2] = w0;
        *(float2*)&ob1[n * 8 + lr * 2] = w1;
    }
}

} // anonymous namespace

// ---------------------------------------------------------------------------
extern "C" void kernel_launch(void* const* d_in, const int* in_sizes, int n_in,
                              void* d_out, int out_size)
{
    const float* x     = (const float*)d_in[0];
    const float* W_qkv = (const float*)d_in[1];
    const float* b_qkv = (const float*)d_in[2];
    const float* W_out = (const float*)d_in[3];
    const float* b_out = (const float*)d_in[4];
    float* out = (float*)d_out;

    float *qp, *kp, *vp, *ctx, *scp;
    cudaGetSymbolAddress((void**)&qp,  g_q);
    cudaGetSymbolAddress((void**)&kp,  g_k);
    cudaGetSymbolAddress((void**)&vp,  g_v);
    cudaGetSymbolAddress((void**)&ctx, g_ctx);
    cudaGetSymbolAddress((void**)&scp, g_sc);

    // 0) sin/cos table
    trig_kernel<<<(T_ * 32) / 256, 256>>>(scp);

    // 1) QKV GEMM with fused bias + RoPE + scatter to [B,H,T,D]
    {
        dim3 grid(3 * C_ / 128, MTOK / 128);
        gemm_tf32<true><<<grid, 128>>>(x, W_qkv, b_qkv, nullptr,
                                       qp, kp, vp, scp, MTOK, 3 * C_, C_);
    }

    // 2) Flash attention (tf32 tensor cores)
    {
        cudaFuncSetAttribute(flash_attn_tf32_kernel,
                             cudaFuncAttributeMaxDynamicSharedMemorySize, SMEM_BYTES);
        dim3 grid(T_ / QB, B_ * NH);
        flash_attn_tf32_kernel<<<grid, 128, SMEM_BYTES>>>(qp, kp, vp, ctx);
    }

    // 3) Output projection
    {
        dim3 grid(C_ / 128, MTOK / 128);
        gemm_tf32<false><<<grid, 128>>>(ctx, W_out, b_out, out,
                                        nullptr, nullptr, nullptr, nullptr,
                                        MTOK, C_, C_);
    }
}

// round 7
// speedup vs baseline: 2.1102x; 1.7048x over previous
#include <cuda_runtime.h>
#include <cuda_fp16.h>
#include <math.h>
#include <stdint.h>

// ---------------------------------------------------------------------------
// RotarySelfAttention: x[B,T,C] -> QKV GEMM(+fused RoPE) -> attention -> proj
// B=2, T=2048, C=1024, H=16, D=64
// Round 7: harness targets sm_100 (no tcgen05). All matmuls moved to
//          mma.sync.m16n8k16.f16 (2x tf32 rate, SAME 10-bit mantissa).
// ---------------------------------------------------------------------------

namespace {

constexpr int B_   = 2;
constexpr int T_   = 2048;
constexpr int C_   = 1024;
constexpr int NH   = 16;
constexpr int HD   = 64;
constexpr int MTOK = B_ * T_;   // 4096

// Scratch (allocation-free rule: __device__ globals)
__device__ __half   g_xh[(size_t)MTOK * C_];            // x fp16 [M][K]
__device__ uint32_t g_wq2[(size_t)(C_ / 2) * 3 * C_];   // W_qkv packed [K/2][3C] half2
__device__ uint32_t g_wo2[(size_t)(C_ / 2) * C_];       // W_out packed [K/2][C] half2
__device__ __half   g_qh[(size_t)B_ * NH * T_ * HD];    // q fp16 [bh][t][d] (scaled)
__device__ uint32_t g_k2[(size_t)B_ * NH * (HD / 2) * T_]; // k packed [bh][d2][t] half2
__device__ __half   g_vh[(size_t)B_ * NH * T_ * HD];    // v fp16 [bh][t][d]
__device__ __half   g_ch[(size_t)MTOK * C_];            // ctx fp16 [M][C]
__device__ float    g_sc[(size_t)T_ * 32 * 2];          // sin/cos [t][d][2]

// ---------------- helpers ----------------
__device__ __forceinline__ void mma_f16(float c[4], const uint32_t a[4],
                                        uint32_t b0, uint32_t b1) {
    asm volatile(
        "mma.sync.aligned.m16n8k16.row.col.f32.f16.f16.f32 "
        "{%0,%1,%2,%3}, {%4,%5,%6,%7}, {%8,%9}, {%0,%1,%2,%3};\n"
        : "+f"(c[0]), "+f"(c[1]), "+f"(c[2]), "+f"(c[3])
        : "r"(a[0]), "r"(a[1]), "r"(a[2]), "r"(a[3]), "r"(b0), "r"(b1));
}

__device__ __forceinline__ uint32_t h2u(__half2 h) {
    return *(uint32_t*)&h;
}

// ---------------------------------------------------------------------------
// trig table
// ---------------------------------------------------------------------------
__global__ __launch_bounds__(256)
void trig_kernel(float* __restrict__ sc)
{
    const int idx = blockIdx.x * 256 + threadIdx.x;   // 65536
    const int d = idx & 31;
    const int t = idx >> 5;
    const float inv_freq = expf((float)d * -0.28782313662425574f); // -ln(1e4)/32
    float s, c;
    sincosf((float)t * inv_freq, &s, &c);
    sc[idx * 2]     = s;
    sc[idx * 2 + 1] = c;
}

// ---------------------------------------------------------------------------
// f32 -> f16 elementwise (4 elems/thread)
// ---------------------------------------------------------------------------
__global__ __launch_bounds__(256)
void f2h_kernel(const float* __restrict__ s, __half* __restrict__ d)
{
    const int i = blockIdx.x * 256 + threadIdx.x;
    const float4 v = ((const float4*)s)[i];
    ((__half2*)d)[i * 2]     = __floats2half2_rn(v.x, v.y);
    ((__half2*)d)[i * 2 + 1] = __floats2half2_rn(v.z, v.w);
}

// ---------------------------------------------------------------------------
// pack W[K][N] f32 -> [K/2][N] u32 half2 (pairs adjacent k rows per column)
// ---------------------------------------------------------------------------
__global__ __launch_bounds__(256)
void wpack_kernel(const float* __restrict__ W, uint32_t* __restrict__ P, int N)
{
    const int i = blockIdx.x * 256 + threadIdx.x;   // over (K/2)*N
    const int n  = i % N;
    const int k2 = i / N;
    const float w0 = W[(size_t)(2 * k2) * N + n];
    const float w1 = W[(size_t)(2 * k2 + 1) * N + n];
    P[i] = h2u(__floats2half2_rn(w0, w1));
}

// ---------------------------------------------------------------------------
// fp16 tensor-core GEMM, double-buffered smem, coalesced loads.
// Block 128x128, BK=32 halves (16 half2 units)/stage, 128 thr, warp tile 64x64.
// A2: [M][K/2] u32 (half2 along k).  B2: [K/2][N] u32.
// As2[m][20] (16 used), Bs2[k2=16][136] (128 used) -> conflict-free frags.
// ROPE=true : epilogue bias+rotary -> q(half)/k(packed)/v(half).
// ROPE=false: epilogue bias -> Cout f32.
// ---------------------------------------------------------------------------
constexpr int GAS = 20;    // As2 row stride (u32)
constexpr int GBS = 136;   // Bs2 row stride (u32)

template<bool ROPE>
__global__ __launch_bounds__(128)
void gemm_f16(const uint32_t* __restrict__ A2,
              const uint32_t* __restrict__ B2,
              const float* __restrict__ bias,
              float* __restrict__ Cout,
              __half* __restrict__ gq,
              uint32_t* __restrict__ gk2,
              __half* __restrict__ gv,
              const float* __restrict__ sc,
              int N, int K2tot)
{
    __shared__ uint32_t As2[2][128 * GAS];
    __shared__ uint32_t Bs2[2][16 * GBS];

    const int tid  = threadIdx.x;
    const int lane = tid & 31;
    const int wid  = tid >> 5;
    const int lq   = lane >> 2;
    const int lr   = lane & 3;

    const int brow = blockIdx.y * 128;
    const int bcol = blockIdx.x * 128;
    const int wm   = (wid & 1) * 64;
    const int wn   = (wid >> 1) * 64;

    const int aRow = tid >> 2;          // 0..31 (+p*32)
    const int aCol = (tid & 3) * 4;     // u32 units 0,4,8,12
    const int bRow = tid >> 3;          // 0..15
    const int bCol = (tid & 7) * 4;     // 0..28 (+j*32)

    float acc[4][8][4];
#pragma unroll
    for (int i = 0; i < 4; i++)
#pragma unroll
        for (int j = 0; j < 8; j++)
#pragma unroll
            for (int t = 0; t < 4; t++) acc[i][j][t] = 0.f;

    uint4 ar[4], br[4];

    // prologue: prefetch + store stage 0
#pragma unroll
    for (int p = 0; p < 4; p++)
        ar[p] = *(const uint4*)&A2[(size_t)(brow + aRow + p * 32) * K2tot + aCol];
#pragma unroll
    for (int j = 0; j < 4; j++)
        br[j] = *(const uint4*)&B2[(size_t)bRow * N + bcol + bCol + j * 32];
#pragma unroll
    for (int p = 0; p < 4; p++)
        *(uint4*)&As2[0][(aRow + p * 32) * GAS + aCol] = ar[p];
#pragma unroll
    for (int j = 0; j < 4; j++)
        *(uint4*)&Bs2[0][bRow * GBS + bCol + j * 32] = br[j];
    __syncthreads();

    const int nst = K2tot / 16;
    for (int s = 0; s < nst; s++) {
        const int st = s & 1;
        const bool more = (s + 1) < nst;
        const int k2n = (s + 1) * 16;

        if (more) {
#pragma unroll
            for (int p = 0; p < 4; p++)
                ar[p] = *(const uint4*)&A2[(size_t)(brow + aRow + p * 32) * K2tot + k2n + aCol];
#pragma unroll
            for (int j = 0; j < 4; j++)
                br[j] = *(const uint4*)&B2[(size_t)(k2n + bRow) * N + bcol + bCol + j * 32];
        }

        // compute: 2 k16-steps (kk2 = 0, 8 half2 units)
#pragma unroll
        for (int kk2 = 0; kk2 < 16; kk2 += 8) {
            uint32_t a[4][4];
#pragma unroll
            for (int i = 0; i < 4; i++) {
                const int m = wm + i * 16 + lq;
                a[i][0] = As2[st][m * GAS + kk2 + lr];
                a[i][1] = As2[st][(m + 8) * GAS + kk2 + lr];
                a[i][2] = As2[st][m * GAS + kk2 + lr + 4];
                a[i][3] = As2[st][(m + 8) * GAS + kk2 + lr + 4];
            }
#pragma unroll
            for (int j = 0; j < 8; j++) {
                const int n = wn + j * 8 + lq;
                const uint32_t b0 = Bs2[st][(kk2 + lr) * GBS + n];
                const uint32_t b1 = Bs2[st][(kk2 + lr + 4) * GBS + n];
#pragma unroll
                for (int i = 0; i < 4; i++)
                    mma_f16(acc[i][j], a[i], b0, b1);
            }
        }

        if (more) {
            const int ns = st ^ 1;
#pragma unroll
            for (int p = 0; p < 4; p++)
                *(uint4*)&As2[ns][(aRow + p * 32) * GAS + aCol] = ar[p];
#pragma unroll
            for (int j = 0; j < 4; j++)
                *(uint4*)&Bs2[ns][bRow * GBS + bCol + j * 32] = br[j];
        }
        __syncthreads();
    }

    if (!ROPE) {
        // ---- plain bias epilogue (f32 out) ----
#pragma unroll
        for (int i = 0; i < 4; i++) {
            const int row0 = brow + wm + i * 16 + lq;
#pragma unroll
            for (int j = 0; j < 8; j++) {
                const int col = bcol + wn + j * 8 + lr * 2;
                const float bi0 = bias[col], bi1 = bias[col + 1];
                float2 w0, w1;
                w0.x = acc[i][j][0] + bi0; w0.y = acc[i][j][1] + bi1;
                w1.x = acc[i][j][2] + bi0; w1.y = acc[i][j][3] + bi1;
                *(float2*)&Cout[(size_t)row0 * N + col]       = w0;
                *(float2*)&Cout[(size_t)(row0 + 8) * N + col] = w1;
            }
        }
    } else {
        // ---- fused RoPE epilogue: bias + rotate + scatter (fp16 outputs) ----
        const int colbase = bcol + wn;            // 64-aligned: one head
        const int region  = colbase >> 10;        // 0=q, 1=k, 2=v
        const int h       = (colbase >> 6) & 15;
        const float scl = (region == 0) ? 0.125f : 1.0f;

#pragma unroll
        for (int i = 0; i < 4; i++) {
            const int rowA = brow + wm + i * 16 + lq;
#pragma unroll
            for (int half_ = 0; half_ < 2; half_++) {
                const int row = rowA + half_ * 8;
                const int t   = row & (T_ - 1);
                const int bb  = row >> 11;
                const int bh  = bb * NH + h;
#pragma unroll
                for (int j = 0; j < 4; j++) {
                    const int d0 = j * 8 + lr * 2;             // 0..30, even
                    const float x10 = acc[i][j][2 * half_ + 0]     + bias[colbase + d0];
                    const float x11 = acc[i][j][2 * half_ + 1]     + bias[colbase + d0 + 1];
                    const float x20 = acc[i][j + 4][2 * half_ + 0] + bias[colbase + d0 + 32];
                    const float x21 = acc[i][j + 4][2 * half_ + 1] + bias[colbase + d0 + 33];
                    float o1x, o1y, o2x, o2y;
                    if (region < 2) {
                        const float2 sc0 = *(const float2*)&sc[(t * 32 + d0) * 2];
                        const float2 sc1 = *(const float2*)&sc[(t * 32 + d0 + 1) * 2];
                        o1x = (x10 * sc0.y - x20 * sc0.x) * scl;
                        o1y = (x11 * sc1.y - x21 * sc1.x) * scl;
                        o2x = (x20 * sc0.y + x10 * sc0.x) * scl;
                        o2y = (x21 * sc1.y + x11 * sc1.x) * scl;
                    } else {
                        o1x = x10; o1y = x11; o2x = x20; o2y = x21;
                    }
                    const __half2 h1 = __floats2half2_rn(o1x, o1y);
                    const __half2 h2 = __floats2half2_rn(o2x, o2y);
                    if (region == 1) {
                        // k packed: [bh][d2][T]
                        uint32_t* kb = gk2 + (size_t)bh * 32 * T_;
                        kb[(d0 >> 1) * T_ + t]        = h2u(h1);
                        kb[((d0 >> 1) + 16) * T_ + t] = h2u(h2);
                    } else {
                        __half* dst = (region == 0) ? gq : gv;
                        __half* drow = dst + ((size_t)bh * T_ + t) * HD;
                        *(__half2*)&drow[d0]      = h1;
                        *(__half2*)&drow[d0 + 32] = h2;
                    }
                }
            }
        }
    }
}

// ---------------------------------------------------------------------------
// Flash attention, fp16 mma.sync m16n8k16, fp32 accumulate.
// Block: 128 threads (4 warps), 64 query rows; KV tiles of 64 keys.
// Ks2 [32 d2][72]: packed half2 over d (from g_k2 [bh][d2][T]).
// Vs2 [32 t2][72]: packed half2 over key parity (packed at load via prmt).
// Ps2 [64][36]  : Q staging then P (half2 over keys).
// ---------------------------------------------------------------------------
constexpr int QB  = 64;
constexpr int KBt = 64;

__global__ __launch_bounds__(128)
void flash_attn_f16_kernel(const __half* __restrict__ q,
                           const uint32_t* __restrict__ k2,
                           const __half* __restrict__ v,
                           __half* __restrict__ ch)
{
    __shared__ uint32_t Ks2[32 * 72];
    __shared__ uint32_t Vs2[32 * 72];
    __shared__ uint32_t Ps2[64 * 36];

    const int tid  = threadIdx.x;
    const int lane = tid & 31;
    const int wid  = tid >> 5;
    const int bh   = blockIdx.y;
    const int b    = bh >> 4;
    const int h    = bh & 15;
    const int q0   = blockIdx.x * QB;

    const int lq = lane >> 2;
    const int lr = lane & 3;
    const int r0 = wid * 16 + lq;

    const float NEG_INF = __int_as_float(0xff800000u);

    // ---- stage Q tile [64][32 u32] into Ps2, pull A-frags ----
    const uint32_t* qb32 = (const uint32_t*)(q + ((size_t)bh * T_ + q0) * HD);
#pragma unroll
    for (int it = 0; it < 4; it++) {
        const int idx = tid + it * 128;          // 512 uint4
        const int row = idx >> 3, c = idx & 7;
        *(uint4*)&Ps2[row * 36 + c * 4] = *(const uint4*)&qb32[(size_t)row * 32 + c * 4];
    }
    __syncthreads();

    uint32_t qf[4][4];
#pragma unroll
    for (int ks = 0; ks < 4; ks++) {
        const int c = ks * 8 + lr;
        qf[ks][0] = Ps2[r0 * 36 + c];
        qf[ks][1] = Ps2[(r0 + 8) * 36 + c];
        qf[ks][2] = Ps2[r0 * 36 + c + 4];
        qf[ks][3] = Ps2[(r0 + 8) * 36 + c + 4];
    }

    float oacc[8][4];
#pragma unroll
    for (int n = 0; n < 8; n++)
#pragma unroll
        for (int j = 0; j < 4; j++) oacc[n][j] = 0.f;
    float m0 = NEG_INF, m1 = NEG_INF, l0 = 0.f, l1 = 0.f;

    const uint32_t* kb = k2 + (size_t)bh * 32 * T_;
    const uint32_t* vb32 = (const uint32_t*)(v + (size_t)bh * T_ * HD);

    for (int kt = 0; kt < T_; kt += KBt) {
        __syncthreads();
        // ---- K tile: [32 d2][64 keys] u32, rows from [d2][T] ----
#pragma unroll
        for (int it = 0; it < 4; it++) {
            const int idx = tid + it * 128;      // 512 uint4
            const int row = idx >> 4, c = idx & 15;
            *(uint4*)&Ks2[row * 72 + c * 4] = *(const uint4*)&kb[(size_t)row * T_ + kt + c * 4];
        }
        // ---- V tile: pack key-parity pairs via prmt ----
#pragma unroll
        for (int it = 0; it < 8; it++) {
            const int idx = tid + it * 128;      // 1024 pair-tasks
            const int t2 = idx >> 5, dp = idx & 31;
            const uint32_t x0 = vb32[(size_t)(kt + 2 * t2) * 32 + dp];
            const uint32_t x1 = vb32[(size_t)(kt + 2 * t2 + 1) * 32 + dp];
            Vs2[t2 * 72 + 2 * dp]     = __byte_perm(x0, x1, 0x5410);
            Vs2[t2 * 72 + 2 * dp + 1] = __byte_perm(x0, x1, 0x7632);
        }
        __syncthreads();

        // ---- S = Q K^T ----
        float sacc[8][4];
#pragma unroll
        for (int n = 0; n < 8; n++)
#pragma unroll
            for (int j = 0; j < 4; j++) sacc[n][j] = 0.f;

#pragma unroll
        for (int ks = 0; ks < 4; ks++) {
#pragma unroll
            for (int n = 0; n < 8; n++) {
                const uint32_t b0 = Ks2[(ks * 8 + lr) * 72 + n * 8 + lq];
                const uint32_t b1 = Ks2[(ks * 8 + lr + 4) * 72 + n * 8 + lq];
                mma_f16(sacc[n], qf[ks], b0, b1);
            }
        }

        // ---- online softmax ----
        float tm0 = NEG_INF, tm1 = NEG_INF;
#pragma unroll
        for (int n = 0; n < 8; n++) {
            tm0 = fmaxf(tm0, fmaxf(sacc[n][0], sacc[n][1]));
            tm1 = fmaxf(tm1, fmaxf(sacc[n][2], sacc[n][3]));
        }
        tm0 = fmaxf(tm0, __shfl_xor_sync(0xffffffffu, tm0, 1));
        tm0 = fmaxf(tm0, __shfl_xor_sync(0xffffffffu, tm0, 2));
        tm1 = fmaxf(tm1, __shfl_xor_sync(0xffffffffu, tm1, 1));
        tm1 = fmaxf(tm1, __shfl_xor_sync(0xffffffffu, tm1, 2));

        const float mn0 = fmaxf(m0, tm0), mn1 = fmaxf(m1, tm1);
        const float a0 = __expf(m0 - mn0), a1 = __expf(m1 - mn1);
        l0 *= a0; l1 *= a1;
#pragma unroll
        for (int n = 0; n < 8; n++) {
            oacc[n][0] *= a0; oacc[n][1] *= a0;
            oacc[n][2] *= a1; oacc[n][3] *= a1;
        }
        m0 = mn0; m1 = mn1;

        // ---- P = exp(S - m) as half2 (keys 2u,2u+1), warp-private rows ----
#pragma unroll
        for (int n = 0; n < 8; n++) {
            const float p0 = __expf(sacc[n][0] - mn0);
            const float p1 = __expf(sacc[n][1] - mn0);
            const float p2 = __expf(sacc[n][2] - mn1);
            const float p3 = __expf(sacc[n][3] - mn1);
            l0 += p0 + p1; l1 += p2 + p3;
            Ps2[r0 * 36 + n * 4 + lr]       = h2u(__floats2half2_rn(p0, p1));
            Ps2[(r0 + 8) * 36 + n * 4 + lr] = h2u(__floats2half2_rn(p2, p3));
        }
        __syncwarp();

        // ---- O += P V ----
#pragma unroll
        for (int ks = 0; ks < 4; ks++) {
            uint32_t af[4];
            af[0] = Ps2[r0 * 36 + ks * 8 + lr];
            af[1] = Ps2[(r0 + 8) * 36 + ks * 8 + lr];
            af[2] = Ps2[r0 * 36 + ks * 8 + lr + 4];
            af[3] = Ps2[(r0 + 8) * 36 + ks * 8 + lr + 4];
#pragma unroll
            for (int n = 0; n < 8; n++) {
                const uint32_t b0 = Vs2[(ks * 8 + lr) * 72 + n * 8 + lq];
                const uint32_t b1 = Vs2[(ks * 8 + lr + 4) * 72 + n * 8 + lq];
                mma_f16(oacc[n], af, b0, b1);
            }
        }
    }

    // ---- epilogue: normalize, write ctx fp16 ----
    l0 += __shfl_xor_sync(0xffffffffu, l0, 1);
    l0 += __shfl_xor_sync(0xffffffffu, l0, 2);
    l1 += __shfl_xor_sync(0xffffffffu, l1, 1);
    l1 += __shfl_xor_sync(0xffffffffu, l1, 2);
    const float inv0 = 1.f / l0, inv1 = 1.f / l1;

    uint32_t* c32 = (uint32_t*)ch;
    const size_t base0 = (((size_t)(b * T_) + q0 + r0) * C_ + h * HD) >> 1;
    const size_t base1 = base0 + (size_t)4 * C_;
#pragma unroll
    for (int n = 0; n < 8; n++) {
        c32[base0 + n * 4 + lr] = h2u(__floats2half2_rn(oacc[n][0] * inv0, oacc[n][1] * inv0));
        c32[base1 + n * 4 + lr] = h2u(__floats2half2_rn(oacc[n][2] * inv1, oacc[n][3] * inv1));
    }
}

} // anonymous namespace

// ---------------------------------------------------------------------------
extern "C" void kernel_launch(void* const* d_in, const int* in_sizes, int n_in,
                              void* d_out, int out_size)
{
    const float* x     = (const float*)d_in[0];
    const float* W_qkv = (const float*)d_in[1];
    const float* b_qkv = (const float*)d_in[2];
    const float* W_out = (const float*)d_in[3];
    const float* b_out = (const float*)d_in[4];
    float* out = (float*)d_out;

    float* scp;
    __half *xh, *qh, *vh, *chp;
    uint32_t *wq2, *wo2, *k2p;
    cudaGetSymbolAddress((void**)&scp, g_sc);
    cudaGetSymbolAddress((void**)&xh,  g_xh);
    cudaGetSymbolAddress((void**)&wq2, g_wq2);
    cudaGetSymbolAddress((void**)&wo2, g_wo2);
    cudaGetSymbolAddress((void**)&qh,  g_qh);
    cudaGetSymbolAddress((void**)&k2p, g_k2);
    cudaGetSymbolAddress((void**)&vh,  g_vh);
    cudaGetSymbolAddress((void**)&chp, g_ch);

    // 0) trig table + input conversions
    trig_kernel<<<(T_ * 32) / 256, 256>>>(scp);
    f2h_kernel<<<(MTOK * C_) / (256 * 4), 256>>>(x, xh);
    wpack_kernel<<<((C_ / 2) * 3 * C_) / 256, 256>>>(W_qkv, wq2, 3 * C_);
    wpack_kernel<<<((C_ / 2) * C_) / 256, 256>>>(W_out, wo2, C_);

    // 1) QKV GEMM (fp16 mma) with fused bias + RoPE + scatter
    {
        dim3 grid(3 * C_ / 128, MTOK / 128);   // (24, 32)
        gemm_f16<true><<<grid, 128>>>((const uint32_t*)xh, wq2, b_qkv, nullptr,
                                      qh, k2p, vh, scp, 3 * C_, C_ / 2);
    }

    // 2) Flash attention (fp16 mma) -> ctx fp16
    {
        dim3 grid(T_ / QB, B_ * NH);
        flash_attn_f16_kernel<<<grid, 128>>>(qh, k2p, vh, chp);
    }

    // 3) Output projection (fp16 mma) -> f32 out
    {
        dim3 grid(C_ / 128, MTOK / 128);       // (8, 32)
        gemm_f16<false><<<grid, 128>>>((const uint32_t*)chp, wo2, b_out, out,
                                       nullptr, nullptr, nullptr, nullptr,
                                       C_, C_ / 2);
    }
}

// round 8
// speedup vs baseline: 2.4117x; 1.1429x over previous
#include <cuda_runtime.h>
#include <cuda_fp16.h>
#include <math.h>
#include <stdint.h>

// ---------------------------------------------------------------------------
// RotarySelfAttention: x[B,T,C] -> QKV GEMM(+fused RoPE) -> attention -> proj
// B=2, T=2048, C=1024, H=16, D=64
// Round 8: cp.async pipelines everywhere. GEMM 3-stage, attention 2-stage
//          K/V double-buffer (V pre-packed [bh][d][t2] by the QKV epilogue).
//          exp2f softmax with log2e folded into q scale. One prep kernel.
// ---------------------------------------------------------------------------

namespace {

constexpr int B_   = 2;
constexpr int T_   = 2048;
constexpr int C_   = 1024;
constexpr int NH   = 16;
constexpr int HD   = 64;
constexpr int MTOK = B_ * T_;   // 4096

// Scratch (allocation-free rule: __device__ globals)
__device__ __half   g_xh[(size_t)MTOK * C_];               // x fp16 [M][K]
__device__ uint32_t g_wq2[(size_t)(C_ / 2) * 3 * C_];      // W_qkv [K/2][3C] half2
__device__ uint32_t g_wo2[(size_t)(C_ / 2) * C_];          // W_out [K/2][C] half2
__device__ __half   g_qh[(size_t)B_ * NH * T_ * HD];       // q [bh][t][d] (scaled by 0.125*log2e)
__device__ uint32_t g_k2[(size_t)B_ * NH * (HD / 2) * T_]; // k [bh][d2][t] half2 over d
__device__ uint32_t g_v2[(size_t)B_ * NH * HD * (T_ / 2)]; // v [bh][d][t2] half2 over t
__device__ __half   g_ch[(size_t)MTOK * C_];               // ctx fp16 [M][C]
__device__ float    g_sc[(size_t)T_ * 32 * 2];             // sin/cos [t][d][2]

// ---------------- helpers ----------------
__device__ __forceinline__ void mma_f16(float c[4], const uint32_t a[4],
                                        uint32_t b0, uint32_t b1) {
    asm volatile(
        "mma.sync.aligned.m16n8k16.row.col.f32.f16.f16.f32 "
        "{%0,%1,%2,%3}, {%4,%5,%6,%7}, {%8,%9}, {%0,%1,%2,%3};\n"
        : "+f"(c[0]), "+f"(c[1]), "+f"(c[2]), "+f"(c[3])
        : "r"(a[0]), "r"(a[1]), "r"(a[2]), "r"(a[3]), "r"(b0), "r"(b1));
}

__device__ __forceinline__ uint32_t h2u(__half2 h) { return *(uint32_t*)&h; }

__device__ __forceinline__ void cp16(void* smem, const void* gmem) {
    uint32_t s = (uint32_t)__cvta_generic_to_shared(smem);
    asm volatile("cp.async.cg.shared.global [%0], [%1], 16;" :: "r"(s), "l"(gmem));
}
__device__ __forceinline__ void cp_commit() {
    asm volatile("cp.async.commit_group;" ::: "memory");
}
__device__ __forceinline__ void cp_wait1() {
    asm volatile("cp.async.wait_group 1;" ::: "memory");
}

// ---------------------------------------------------------------------------
// One prep kernel: f2h(x), pack W_qkv, pack W_out, trig table.
// grid = 4096 + 6144 + 2048 + 256 = 12544 blocks of 256.
// ---------------------------------------------------------------------------
__global__ __launch_bounds__(256)
void prep_kernel(const float* __restrict__ x,
                 const float* __restrict__ Wq,
                 const float* __restrict__ Wo,
                 __half* __restrict__ xh,
                 uint32_t* __restrict__ wq2,
                 uint32_t* __restrict__ wo2,
                 float* __restrict__ sc)
{
    const int blk = blockIdx.x;
    if (blk < 4096) {
        const int i = blk * 256 + threadIdx.x;
        const float4 v = ((const float4*)x)[i];
        ((__half2*)xh)[i * 2]     = __floats2half2_rn(v.x, v.y);
        ((__half2*)xh)[i * 2 + 1] = __floats2half2_rn(v.z, v.w);
    } else if (blk < 10240) {
        const int i = (blk - 4096) * 256 + threadIdx.x;   // over 512*3072
        const int n  = i % (3 * C_);
        const int k2 = i / (3 * C_);
        wq2[i] = h2u(__floats2half2_rn(Wq[(size_t)(2 * k2) * (3 * C_) + n],
                                       Wq[(size_t)(2 * k2 + 1) * (3 * C_) + n]));
    } else if (blk < 12288) {
        const int i = (blk - 10240) * 256 + threadIdx.x;  // over 512*1024
        const int n  = i & (C_ - 1);
        const int k2 = i >> 10;
        wo2[i] = h2u(__floats2half2_rn(Wo[(size_t)(2 * k2) * C_ + n],
                                       Wo[(size_t)(2 * k2 + 1) * C_ + n]));
    } else {
        const int idx = (blk - 12288) * 256 + threadIdx.x; // 65536
        const int d = idx & 31;
        const int t = idx >> 5;
        const float inv_freq = expf((float)d * -0.28782313662425574f); // -ln(1e4)/32
        float s, c;
        sincosf((float)t * inv_freq, &s, &c);
        sc[idx * 2]     = s;
        sc[idx * 2 + 1] = c;
    }
}

// ---------------------------------------------------------------------------
// fp16 tensor-core GEMM, 3-stage cp.async pipeline.
// Block 128x128, BK=32 halves (16 u32)/stage, 128 thr, warp tile 64x64.
// As[s][m][20] (16 used), Bs[s][k2=16][136] (128 used) -> conflict-free frags.
// ROPE=true : epilogue bias+rotary -> q(half,[bh][t][d]) / k([bh][d2][t]) /
//             v([bh][d][t2], packed via lane shuffles).
// ROPE=false: epilogue bias -> Cout f32.
// ---------------------------------------------------------------------------
constexpr int GAS = 20;    // As row stride (u32)
constexpr int GBS = 136;   // Bs row stride (u32)
constexpr int GEMM_SMEM = 3 * (128 * GAS + 16 * GBS) * 4;  // 56832 B

template<bool ROPE>
__global__ __launch_bounds__(128)
void gemm_f16(const uint32_t* __restrict__ A2,
              const uint32_t* __restrict__ B2,
              const float* __restrict__ bias,
              float* __restrict__ Cout,
              __half* __restrict__ gq,
              uint32_t* __restrict__ gk2,
              uint32_t* __restrict__ gv2,
              const float* __restrict__ sc,
              int N, int K2tot)
{
    extern __shared__ uint32_t gsm[];
    uint32_t* As = gsm;                    // [3][128*GAS]
    uint32_t* Bs = gsm + 3 * 128 * GAS;    // [3][16*GBS]

    const int tid  = threadIdx.x;
    const int lane = tid & 31;
    const int wid  = tid >> 5;
    const int lq   = lane >> 2;
    const int lr   = lane & 3;

    const int brow = blockIdx.y * 128;
    const int bcol = blockIdx.x * 128;
    const int wm   = (wid & 1) * 64;
    const int wn   = (wid >> 1) * 64;

    float acc[4][8][4];
#pragma unroll
    for (int i = 0; i < 4; i++)
#pragma unroll
        for (int j = 0; j < 8; j++)
#pragma unroll
            for (int t = 0; t < 4; t++) acc[i][j][t] = 0.f;

    auto load_stage = [&](int s, int k2b) {
#pragma unroll
        for (int it = 0; it < 4; it++) {
            const int idx = tid + it * 128;           // 512: A 128 rows x 4 chunks
            const int row = idx >> 2, c = idx & 3;
            cp16(&As[s * (128 * GAS) + row * GAS + c * 4],
                 &A2[(size_t)(brow + row) * K2tot + k2b + c * 4]);
        }
#pragma unroll
        for (int it = 0; it < 4; it++) {
            const int idx = tid + it * 128;           // 512: B 16 rows x 32 chunks
            const int row = idx >> 5, c = idx & 31;
            cp16(&Bs[s * (16 * GBS) + row * GBS + c * 4],
                 &B2[(size_t)(k2b + row) * N + bcol + c * 4]);
        }
        cp_commit();
    };

    load_stage(0, 0);
    load_stage(1, 16);

    const int nst = K2tot / 16;
    for (int s = 0; s < nst; s++) {
        cp_wait1();
        __syncthreads();
        if (s + 2 < nst) load_stage((s + 2) % 3, (s + 2) * 16);

        const uint32_t* Asb = As + (s % 3) * (128 * GAS);
        const uint32_t* Bsb = Bs + (s % 3) * (16 * GBS);
#pragma unroll
        for (int kk2 = 0; kk2 < 16; kk2 += 8) {
            uint32_t a[4][4];
#pragma unroll
            for (int i = 0; i < 4; i++) {
                const int m = wm + i * 16 + lq;
                a[i][0] = Asb[m * GAS + kk2 + lr];
                a[i][1] = Asb[(m + 8) * GAS + kk2 + lr];
                a[i][2] = Asb[m * GAS + kk2 + lr + 4];
                a[i][3] = Asb[(m + 8) * GAS + kk2 + lr + 4];
            }
#pragma unroll
            for (int j = 0; j < 8; j++) {
                const int n = wn + j * 8 + lq;
                const uint32_t b0 = Bsb[(kk2 + lr) * GBS + n];
                const uint32_t b1 = Bsb[(kk2 + lr + 4) * GBS + n];
#pragma unroll
                for (int i = 0; i < 4; i++)
                    mma_f16(acc[i][j], a[i], b0, b1);
            }
        }
    }

    if (!ROPE) {
        // ---- plain bias epilogue (f32 out) ----
#pragma unroll
        for (int i = 0; i < 4; i++) {
            const int row0 = brow + wm + i * 16 + lq;
#pragma unroll
            for (int j = 0; j < 8; j++) {
                const int col = bcol + wn + j * 8 + lr * 2;
                const float bi0 = bias[col], bi1 = bias[col + 1];
                float2 w0, w1;
                w0.x = acc[i][j][0] + bi0; w0.y = acc[i][j][1] + bi1;
                w1.x = acc[i][j][2] + bi0; w1.y = acc[i][j][3] + bi1;
                *(float2*)&Cout[(size_t)row0 * N + col]       = w0;
                *(float2*)&Cout[(size_t)(row0 + 8) * N + col] = w1;
            }
        }
    } else {
        // ---- fused RoPE epilogue ----
        const int colbase = bcol + wn;            // 64-aligned: one head
        const int region  = colbase >> 10;        // 0=q, 1=k, 2=v
        const int h       = (colbase >> 6) & 15;
        // q pre-scaled by HD^-0.5 * log2(e) (softmax done in base 2)
        const float scl = (region == 0) ? 0.125f * 1.4426950408889634f : 1.0f;

#pragma unroll
        for (int i = 0; i < 4; i++) {
            const int rowA = brow + wm + i * 16 + lq;
#pragma unroll
            for (int half_ = 0; half_ < 2; half_++) {
                const int row = rowA + half_ * 8;
                const int t   = row & (T_ - 1);
                const int bb  = row >> 11;
                const int bh  = bb * NH + h;
#pragma unroll
                for (int j = 0; j < 4; j++) {
                    const int d0 = j * 8 + lr * 2;             // 0..30, even
                    const float x10 = acc[i][j][2 * half_ + 0]     + bias[colbase + d0];
                    const float x11 = acc[i][j][2 * half_ + 1]     + bias[colbase + d0 + 1];
                    const float x20 = acc[i][j + 4][2 * half_ + 0] + bias[colbase + d0 + 32];
                    const float x21 = acc[i][j + 4][2 * half_ + 1] + bias[colbase + d0 + 33];
                    float o1x, o1y, o2x, o2y;
                    if (region < 2) {
                        const float2 sc0 = *(const float2*)&sc[(t * 32 + d0) * 2];
                        const float2 sc1 = *(const float2*)&sc[(t * 32 + d0 + 1) * 2];
                        o1x = (x10 * sc0.y - x20 * sc0.x) * scl;
                        o1y = (x11 * sc1.y - x21 * sc1.x) * scl;
                        o2x = (x20 * sc0.y + x10 * sc0.x) * scl;
                        o2y = (x21 * sc1.y + x11 * sc1.x) * scl;
                    } else {
                        o1x = x10; o1y = x11; o2x = x20; o2y = x21;
                    }
                    const uint32_t u1 = h2u(__floats2half2_rn(o1x, o1y));
                    const uint32_t u2 = h2u(__floats2half2_rn(o2x, o2y));
                    if (region == 0) {
                        __half* drow = gq + ((size_t)bh * T_ + t) * HD;
                        *(uint32_t*)&drow[d0]      = u1;
                        *(uint32_t*)&drow[d0 + 32] = u2;
                    } else if (region == 1) {
                        // k packed: [bh][d2][T]
                        uint32_t* kb = gk2 + (size_t)bh * 32 * T_;
                        kb[(d0 >> 1) * T_ + t]        = u1;
                        kb[((d0 >> 1) + 16) * T_ + t] = u2;
                    } else {
                        // v packed: [bh][d][T/2]. Pair adjacent-t lanes
                        // (lq even <-> lq+1, lane distance 4) via shuffles.
                        const uint32_t p1 = __shfl_down_sync(0xffffffffu, u1, 4);
                        const uint32_t p2 = __shfl_down_sync(0xffffffffu, u2, 4);
                        if ((lq & 1) == 0) {
                            uint32_t* vb = gv2 + (size_t)bh * HD * (T_ / 2);
                            const int t2 = t >> 1;
                            vb[(size_t)d0 * (T_ / 2) + t2]        = __byte_perm(u1, p1, 0x5410);
                            vb[(size_t)(d0 + 1) * (T_ / 2) + t2]  = __byte_perm(u1, p1, 0x7632);
                            vb[(size_t)(d0 + 32) * (T_ / 2) + t2] = __byte_perm(u2, p2, 0x5410);
                            vb[(size_t)(d0 + 33) * (T_ / 2) + t2] = __byte_perm(u2, p2, 0x7632);
                        }
                    }
                }
            }
        }
    }
}

// ---------------------------------------------------------------------------
// Flash attention, fp16 mma m16n8k16, fp32 accumulate, base-2 softmax.
// Block: 128 threads (4 warps), 64 query rows; KV tiles of 64 keys,
// 2-stage cp.async double buffer.
// Ks2 [2][32 d2][72]: K packed half2 over d ([bh][d2][T] rows).
// Vs2 [2][64 d][36] : V packed half2 over t ([bh][d][T/2] rows).
// Ps2 [64][36]      : Q staging then P (half2 over keys).
// ---------------------------------------------------------------------------
constexpr int QB  = 64;
constexpr int KBt = 64;

__global__ __launch_bounds__(128)
void flash_attn_f16_kernel(const __half* __restrict__ q,
                           const uint32_t* __restrict__ k2,
                           const uint32_t* __restrict__ v2,
                           __half* __restrict__ ch)
{
    __shared__ __align__(16) uint32_t Ks2[2][32 * 72];
    __shared__ __align__(16) uint32_t Vs2[2][64 * 36];
    __shared__ __align__(16) uint32_t Ps2[64 * 36];

    const int tid  = threadIdx.x;
    const int lane = tid & 31;
    const int wid  = tid >> 5;
    const int bh   = blockIdx.y;
    const int b    = bh >> 4;
    const int h    = bh & 15;
    const int q0   = blockIdx.x * QB;

    const int lq = lane >> 2;
    const int lr = lane & 3;
    const int r0 = wid * 16 + lq;

    const float NEG_INF = __int_as_float(0xff800000u);

    const uint32_t* kb  = k2 + (size_t)bh * 32 * T_;
    const uint32_t* vb2 = v2 + (size_t)bh * HD * (T_ / 2);

    auto load_kv = [&](int s, int kt) {
#pragma unroll
        for (int it = 0; it < 4; it++) {
            const int idx = tid + it * 128;         // K: 32 rows x 16 chunks
            const int row = idx >> 4, c = idx & 15;
            cp16(&Ks2[s][row * 72 + c * 4], &kb[(size_t)row * T_ + kt + c * 4]);
        }
#pragma unroll
        for (int it = 0; it < 4; it++) {
            const int idx = tid + it * 128;         // V: 64 rows x 8 chunks
            const int row = idx >> 3, c = idx & 7;
            cp16(&Vs2[s][row * 36 + c * 4], &vb2[(size_t)row * (T_ / 2) + (kt >> 1) + c * 4]);
        }
        cp_commit();
    };

    load_kv(0, 0);
    load_kv(1, KBt);

    // ---- stage Q tile [64][32 u32] into Ps2, pull A-frags ----
    const uint32_t* qb32 = (const uint32_t*)(q + ((size_t)bh * T_ + q0) * HD);
#pragma unroll
    for (int it = 0; it < 4; it++) {
        const int idx = tid + it * 128;          // 512 uint4
        const int row = idx >> 3, c = idx & 7;
        *(uint4*)&Ps2[row * 36 + c * 4] = *(const uint4*)&qb32[(size_t)row * 32 + c * 4];
    }
    __syncthreads();

    uint32_t qf[4][4];
#pragma unroll
    for (int ks = 0; ks < 4; ks++) {
        const int c = ks * 8 + lr;
        qf[ks][0] = Ps2[r0 * 36 + c];
        qf[ks][1] = Ps2[(r0 + 8) * 36 + c];
        qf[ks][2] = Ps2[r0 * 36 + c + 4];
        qf[ks][3] = Ps2[(r0 + 8) * 36 + c + 4];
    }

    float oacc[8][4];
#pragma unroll
    for (int n = 0; n < 8; n++)
#pragma unroll
        for (int j = 0; j < 4; j++) oacc[n][j] = 0.f;
    float m0 = NEG_INF, m1 = NEG_INF, l0 = 0.f, l1 = 0.f;

    for (int ti = 0; ti < T_ / KBt; ti++) {
        cp_wait1();
        __syncthreads();
        const uint32_t* Kt = Ks2[ti & 1];
        const uint32_t* Vt = Vs2[ti & 1];

        // ---- S = Q K^T ----
        float sacc[8][4];
#pragma unroll
        for (int n = 0; n < 8; n++)
#pragma unroll
            for (int j = 0; j < 4; j++) sacc[n][j] = 0.f;

#pragma unroll
        for (int ks = 0; ks < 4; ks++) {
#pragma unroll
            for (int n = 0; n < 8; n++) {
                const uint32_t b0 = Kt[(ks * 8 + lr) * 72 + n * 8 + lq];
                const uint32_t b1 = Kt[(ks * 8 + lr + 4) * 72 + n * 8 + lq];
                mma_f16(sacc[n], qf[ks], b0, b1);
            }
        }

        // ---- online softmax (base 2; q carries log2e) ----
        float tm0 = NEG_INF, tm1 = NEG_INF;
#pragma unroll
        for (int n = 0; n < 8; n++) {
            tm0 = fmaxf(tm0, fmaxf(sacc[n][0], sacc[n][1]));
            tm1 = fmaxf(tm1, fmaxf(sacc[n][2], sacc[n][3]));
        }
        tm0 = fmaxf(tm0, __shfl_xor_sync(0xffffffffu, tm0, 1));
        tm0 = fmaxf(tm0, __shfl_xor_sync(0xffffffffu, tm0, 2));
        tm1 = fmaxf(tm1, __shfl_xor_sync(0xffffffffu, tm1, 1));
        tm1 = fmaxf(tm1, __shfl_xor_sync(0xffffffffu, tm1, 2));

        const float mn0 = fmaxf(m0, tm0), mn1 = fmaxf(m1, tm1);
        const float a0 = exp2f(m0 - mn0), a1 = exp2f(m1 - mn1);
        l0 *= a0; l1 *= a1;
#pragma unroll
        for (int n = 0; n < 8; n++) {
            oacc[n][0] *= a0; oacc[n][1] *= a0;
            oacc[n][2] *= a1; oacc[n][3] *= a1;
        }
        m0 = mn0; m1 = mn1;

        // ---- P = 2^(S - m) as half2 (keys 2u,2u+1), warp-private rows ----
#pragma unroll
        for (int n = 0; n < 8; n++) {
            const float p0 = exp2f(sacc[n][0] - mn0);
            const float p1 = exp2f(sacc[n][1] - mn0);
            const float p2 = exp2f(sacc[n][2] - mn1);
            const float p3 = exp2f(sacc[n][3] - mn1);
            l0 += p0 + p1; l1 += p2 + p3;
            Ps2[r0 * 36 + n * 4 + lr]       = h2u(__floats2half2_rn(p0, p1));
            Ps2[(r0 + 8) * 36 + n * 4 + lr] = h2u(__floats2half2_rn(p2, p3));
        }
        __syncwarp();

        // ---- O += P V ----
#pragma unroll
        for (int ks = 0; ks < 4; ks++) {
            uint32_t af[4];
            af[0] = Ps2[r0 * 36 + ks * 8 + lr];
            af[1] = Ps2[(r0 + 8) * 36 + ks * 8 + lr];
            af[2] = Ps2[r0 * 36 + ks * 8 + lr + 4];
            af[3] = Ps2[(r0 + 8) * 36 + ks * 8 + lr + 4];
#pragma unroll
            for (int n = 0; n < 8; n++) {
                const uint32_t b0 = Vt[(n * 8 + lq) * 36 + ks * 8 + lr];
                const uint32_t b1 = Vt[(n * 8 + lq) * 36 + ks * 8 + lr + 4];
                mma_f16(oacc[n], af, b0, b1);
            }
        }

        __syncthreads();
        if (ti + 2 < T_ / KBt) load_kv(ti & 1, (ti + 2) * KBt);
    }

    // ---- epilogue: normalize, write ctx fp16 ----
    l0 += __shfl_xor_sync(0xffffffffu, l0, 1);
    l0 += __shfl_xor_sync(0xffffffffu, l0, 2);
    l1 += __shfl_xor_sync(0xffffffffu, l1, 1);
    l1 += __shfl_xor_sync(0xffffffffu, l1, 2);
    const float inv0 = 1.f / l0, inv1 = 1.f / l1;

    uint32_t* c32 = (uint32_t*)ch;
    const size_t base0 = (((size_t)(b * T_) + q0 + r0) * C_ + h * HD) >> 1;
    const size_t base1 = base0 + (size_t)4 * C_;
#pragma unroll
    for (int n = 0; n < 8; n++) {
        c32[base0 + n * 4 + lr] = h2u(__floats2half2_rn(oacc[n][0] * inv0, oacc[n][1] * inv0));
        c32[base1 + n * 4 + lr] = h2u(__floats2half2_rn(oacc[n][2] * inv1, oacc[n][3] * inv1));
    }
}

} // anonymous namespace

// ---------------------------------------------------------------------------
extern "C" void kernel_launch(void* const* d_in, const int* in_sizes, int n_in,
                              void* d_out, int out_size)
{
    const float* x     = (const float*)d_in[0];
    const float* W_qkv = (const float*)d_in[1];
    const float* b_qkv = (const float*)d_in[2];
    const float* W_out = (const float*)d_in[3];
    const float* b_out = (const float*)d_in[4];
    float* out = (float*)d_out;

    float* scp;
    __half *xh, *qh, *chp;
    uint32_t *wq2, *wo2, *k2p, *v2p;
    cudaGetSymbolAddress((void**)&scp, g_sc);
    cudaGetSymbolAddress((void**)&xh,  g_xh);
    cudaGetSymbolAddress((void**)&wq2, g_wq2);
    cudaGetSymbolAddress((void**)&wo2, g_wo2);
    cudaGetSymbolAddress((void**)&qh,  g_qh);
    cudaGetSymbolAddress((void**)&k2p, g_k2);
    cudaGetSymbolAddress((void**)&v2p, g_v2);
    cudaGetSymbolAddress((void**)&chp, g_ch);

    cudaFuncSetAttribute(gemm_f16<true>,
                         cudaFuncAttributeMaxDynamicSharedMemorySize, GEMM_SMEM);
    cudaFuncSetAttribute(gemm_f16<false>,
                         cudaFuncAttributeMaxDynamicSharedMemorySize, GEMM_SMEM);

    // 0) prep: f2h(x), pack weights, trig table (one launch)
    prep_kernel<<<12544, 256>>>(x, W_qkv, W_out, xh, wq2, wo2, scp);

    // 1) QKV GEMM (fp16 mma, cp.async x3) with fused bias + RoPE + scatter
    {
        dim3 grid(3 * C_ / 128, MTOK / 128);   // (24, 32)
        gemm_f16<true><<<grid, 128, GEMM_SMEM>>>((const uint32_t*)xh, wq2, b_qkv,
                                                 nullptr, qh, k2p, v2p, scp,
                                                 3 * C_, C_ / 2);
    }

    // 2) Flash attention (fp16 mma, cp.async x2) -> ctx fp16
    {
        dim3 grid(T_ / QB, B_ * NH);
        flash_attn_f16_kernel<<<grid, 128>>>(qh, k2p, v2p, chp);
    }

    // 3) Output projection (fp16 mma, cp.async x3) -> f32 out
    {
        dim3 grid(C_ / 128, MTOK / 128);       // (8, 32)
        gemm_f16<false><<<grid, 128, GEMM_SMEM>>>((const uint32_t*)chp, wo2, b_out,
                                                  out, nullptr, nullptr, nullptr,
                                                  nullptr, C_, C_ / 2);
    }
}